// round 3
// baseline (speedup 1.0000x reference)
#include <cuda_runtime.h>

// Output layout (66 floats): trace[64] then gates[2].
//
// Dead-code analysis of the reference (validated rounds 1-2, rel_err = 0.0):
// the color-refinement trace is independent of x, weights, and edge
// placement — col evolves all-0 -> all-1 -> all-2, mask is always all-true,
// sig_mean[new_c] = E/N exactly each layer. Hence trace[1] = E/(4N),
// trace[2] = E/(2N), rest 0. gates = sigmoid(alpha_i). The GIN MLP stack is
// dead code with respect to the returned values.
//
// This round: instruction-count floor. One warp; lane 0 issues both alpha
// LDGs back-to-back (independent, fully overlapped), computes both sigmoids,
// and stores gates as one STG.64. Lanes 0-15 do the 16x STG.128 zero fill.
// Total: 2 LDG, 17 STG, 2 MUFU.

__global__ void __launch_bounds__(32, 1)
bfs_refine_out_kernel(const float* __restrict__ alpha0,
                      const float* __restrict__ alpha1,
                      float t1, float t2,
                      float* __restrict__ out)
{
    const int i = threadIdx.x;

    if (i == 0) {
        // Both loads issue immediately and overlap.
        const float a0 = __ldg(alpha0);
        const float a1 = __ldg(alpha1);

        // trace[0..3] with the two nonzeros.
        reinterpret_cast<float4*>(out)[0] = make_float4(0.0f, t1, t2, 0.0f);

        // gates as one 8-byte store.
        const float g0 = 1.0f / (1.0f + __expf(-a0));
        const float g1 = 1.0f / (1.0f + __expf(-a1));
        reinterpret_cast<float2*>(out + 64)[0] = make_float2(g0, g1);
    } else if (i < 16) {
        reinterpret_cast<float4*>(out)[i] = make_float4(0.0f, 0.0f, 0.0f, 0.0f);
    }
}

extern "C" void kernel_launch(void* const* d_in, const int* in_sizes, int n_in,
                              void* d_out, int out_size)
{
    // Input order: x, edge_index, W1_0, b1_0, W2_0, b2_0, alpha_0,
    //              W1_1, b1_1, W2_1, b2_1, alpha_1
    const float* alpha0 = (const float*)d_in[6];
    const float* alpha1 = (const float*)d_in[11];

    const long long n_nodes = (long long)in_sizes[0] / 127;  // x is [N, 127]
    const long long n_edges = (long long)in_sizes[1] / 2;    // edge_index is [2, E]

    const double ratio = (double)n_edges / (double)n_nodes;  // E/N
    const float t1 = (float)(ratio * 0.25);  // trace[1] = E/(4N)
    const float t2 = (float)(ratio * 0.5);   // trace[2] = E/(2N)

    bfs_refine_out_kernel<<<1, 32>>>(alpha0, alpha1, t1, t2, (float*)d_out);
}

// round 4
// speedup vs baseline: 4.9931x; 4.9931x over previous
#include <cuda_runtime.h>

// Output layout (66 floats): trace[64] then gates[2].
//
// Dead-code analysis of the reference (validated rounds 1-3, rel_err = 0.0):
// the color-refinement trace is independent of x, weights, and edge
// placement — col evolves all-0 -> all-1 -> all-2, mask is always all-true,
// and sig_mean[new_c] = E/N exactly each layer. Hence trace[1] = E/(4N),
// trace[2] = E/(2N), rest 0. gates = sigmoid(alpha_i). The GIN MLP stack is
// dead code with respect to the returned values.
//
// Structure (best measured variant, round 2 = 3.808us ncu): fully parallel
// single warp. Lane k<16: one STG.128 of the zero/const region. Lane 0/1:
// own LDG(alpha) -> MUFU -> STG.32 gate, independent chains, no cross-lane
// dependency. Critical path per lane = LDG + sigmoid + 1 store.

__global__ void __launch_bounds__(32, 1)
bfs_refine_out_kernel(const float* __restrict__ alpha0,
                      const float* __restrict__ alpha1,
                      float t1, float t2,
                      float* __restrict__ out)
{
    const int i = threadIdx.x;

    // Lanes 0/1: issue alpha loads in the first issue slots.
    float a = 0.0f;
    if (i == 0) a = __ldg(alpha0);
    if (i == 1) a = __ldg(alpha1);

    // Lanes 0..15: 16x STG.128 zero-fill of trace[0..63], independent of the
    // loads above (no register dependency), so they issue while LDG is in
    // flight.
    if (i < 16) {
        float4 v = make_float4(0.0f, 0.0f, 0.0f, 0.0f);
        if (i == 0) { v.y = t1; v.z = t2; }
        reinterpret_cast<float4*>(out)[i] = v;
    }

    // Lanes 0/1: gate stores, each lane its own sigmoid + STG.32.
    if (i < 2) {
        out[64 + i] = 1.0f / (1.0f + __expf(-a));
    }
}

extern "C" void kernel_launch(void* const* d_in, const int* in_sizes, int n_in,
                              void* d_out, int out_size)
{
    // Input order: x, edge_index, W1_0, b1_0, W2_0, b2_0, alpha_0,
    //              W1_1, b1_1, W2_1, b2_1, alpha_1
    const float* alpha0 = (const float*)d_in[6];
    const float* alpha1 = (const float*)d_in[11];

    const long long n_nodes = (long long)in_sizes[0] / 127;  // x is [N, 127]
    const long long n_edges = (long long)in_sizes[1] / 2;    // edge_index is [2, E]

    const double ratio = (double)n_edges / (double)n_nodes;  // E/N
    const float t1 = (float)(ratio * 0.25);  // trace[1] = E/(4N)
    const float t2 = (float)(ratio * 0.5);   // trace[2] = E/(2N)

    bfs_refine_out_kernel<<<1, 32>>>(alpha0, alpha1, t1, t2, (float*)d_out);
}